// round 4
// baseline (speedup 1.0000x reference)
#include <cuda_runtime.h>
#include <math.h>

#define NN 25000
#define EE 400000
#define HH 128
#define DD 64
#define MM 192
#define LLAYERS 3
#define EPSV 1e-6f

// ---------------- persistent device scratch ----------------
__device__ float g_x [NN*HH];
__device__ float g_p [NN*3];
__device__ float g_xn[NN*HH];
__device__ float g_pn[NN*3];
__device__ float g_sa[NN*HH];
__device__ float g_va[NN*3];
__device__ float g_Ws [LLAYERS*MM*HH];
__device__ float g_Wv [LLAYERS*MM*HH];
__device__ float g_bs [LLAYERS*HH];
__device__ float g_bv [LLAYERS*HH];
__device__ float g_csa[LLAYERS*HH];

__device__ __forceinline__ float sigmoidf_(float x){ return 1.f/(1.f + expf(-x)); }
__device__ __forceinline__ float siluf_(float x){ return x/(1.f + expf(-x)); }

__device__ __forceinline__ void zero_acc(float acc[4][8]){
    #pragma unroll
    for (int i = 0; i < 4; ++i){
        #pragma unroll
        for (int j = 0; j < 8; ++j) acc[i][j] = 0.f;
    }
}

// ---------------- small prep kernels ----------------
__global__ void copy_init(const float* __restrict__ x, const float* __restrict__ pos, int N){
    int i = blockIdx.x*blockDim.x + threadIdx.x;
    if (i < N*HH) g_x[i] = x[i];
    if (i < N*3)  g_p[i] = pos[i];
}

__global__ void zero_aggr(int N){
    int i = blockIdx.x*blockDim.x + threadIdx.x;
    if (i < N*HH) g_sa[i] = 0.f;
    if (i < N*3)  g_va[i] = 0.f;
}

// fold LN gains into weights: Ws = diag(s_ln1_g)*s_w1, Wv = diag(v_ln_g)*v_w1
__global__ void fold_w(const float* __restrict__ sw1, const float* __restrict__ sg,
                       const float* __restrict__ vw1, const float* __restrict__ vg){
    int i = blockIdx.x*blockDim.x + threadIdx.x;
    if (i >= LLAYERS*MM*HH) return;
    int l = i/(MM*HH);
    int k = (i/HH)%MM;
    g_Ws[i] = sg[l*MM+k]*sw1[i];
    g_Wv[i] = vg[l*MM+k]*vw1[i];
}

// fold LN biases into GEMM biases; colsum of a_w1 for the raw-msg path
__global__ void fold_bias(const float* __restrict__ sw1, const float* __restrict__ sb1, const float* __restrict__ slb,
                          const float* __restrict__ vw1, const float* __restrict__ vb1, const float* __restrict__ vlb,
                          const float* __restrict__ aw1){
    int i = blockIdx.x*blockDim.x + threadIdx.x;
    if (i >= LLAYERS*HH) return;
    int l = i/HH, c = i%HH;
    float bs = sb1[i], bv = vb1[i], cs = 0.f;
    for (int k = 0; k < MM; ++k){
        float swv = sw1[(l*MM+k)*HH + c];
        float vwv = vw1[(l*MM+k)*HH + c];
        bs += slb[l*MM+k]*swv;
        bv += vlb[l*MM+k]*vwv;
        cs += aw1[(l*MM+k)*HH + c];
    }
    g_bs[i] = bs; g_bv[i] = bv; g_csa[i] = cs;
}

// per-node LayerNorm of x (H=128) and pos (3). warp per node.
__global__ void ln_node(const float* __restrict__ lxg, const float* __restrict__ lxb,
                        const float* __restrict__ lpg, const float* __restrict__ lpb, int N){
    int w = (blockIdx.x*blockDim.x + threadIdx.x) >> 5;
    int lane = threadIdx.x & 31;
    if (w >= N) return;
    float v[4]; float s = 0.f, q = 0.f;
    #pragma unroll
    for (int j = 0; j < 4; ++j){
        v[j] = g_x[w*HH + (j<<5) + lane];
        s += v[j]; q += v[j]*v[j];
    }
    #pragma unroll
    for (int o = 16; o; o >>= 1){
        s += __shfl_xor_sync(0xffffffffu, s, o);
        q += __shfl_xor_sync(0xffffffffu, q, o);
    }
    float mean = s*(1.f/128.f);
    float var  = fmaxf(q*(1.f/128.f) - mean*mean, 0.f);
    float rstd = rsqrtf(var + EPSV);
    #pragma unroll
    for (int j = 0; j < 4; ++j){
        int c = (j<<5) + lane;
        g_xn[w*HH + c] = (v[j]-mean)*rstd*lxg[c] + lxb[c];
    }
    if (lane == 0){
        float p0 = g_p[w*3+0], p1 = g_p[w*3+1], p2 = g_p[w*3+2];
        float m = (p0+p1+p2)*(1.f/3.f);
        float d0 = p0-m, d1 = p1-m, d2 = p2-m;
        float varp = (d0*d0+d1*d1+d2*d2)*(1.f/3.f);
        float rs = rsqrtf(varp + EPSV);
        g_pn[w*3+0] = d0*rs*lpg[0] + lpb[0];
        g_pn[w*3+1] = d1*rs*lpg[1] + lpb[1];
        g_pn[w*3+2] = d2*rs*lpg[2] + lpb[2];
    }
}

// ---------------- fused edge kernel ----------------
// 64 edges per block, 256 threads (16x16): thread tile = 4 edges x 8 cols.
__device__ __forceinline__ void fma_tile8x4(float acc[4][8], float4 a, float4 w0, float4 w1){
    float av[4] = {a.x, a.y, a.z, a.w};
    float wv[8] = {w0.x, w0.y, w0.z, w0.w, w1.x, w1.y, w1.z, w1.w};
    #pragma unroll
    for (int i = 0; i < 4; ++i)
        #pragma unroll
        for (int j = 0; j < 8; ++j)
            acc[i][j] = fmaf(av[i], wv[j], acc[i][j]);
}

template<int K>
__device__ __forceinline__ void gemm_msg(const float* __restrict__ shmsg,
                                         const float* __restrict__ W,
                                         int ty, int tx, float acc[4][8]){
    const float4* msg4 = (const float4*)shmsg;   // [K][16] float4, row = k
    const float4* W4   = (const float4*)W;       // [K][32] float4
    float4 a  = msg4[ty];
    float4 w0 = __ldg(W4 + (tx<<1));
    float4 w1 = __ldg(W4 + (tx<<1) + 1);
    #pragma unroll 2
    for (int k = 0; k < K-1; ++k){
        float4 an  = msg4[(k+1)*16 + ty];
        float4 w0n = __ldg(W4 + (k+1)*32 + (tx<<1));
        float4 w1n = __ldg(W4 + (k+1)*32 + (tx<<1) + 1);
        fma_tile8x4(acc, a, w0, w1);
        a = an; w0 = w0n; w1 = w1n;
    }
    fma_tile8x4(acc, a, w0, w1);
}

__device__ __forceinline__ void gemm_hs(const float* __restrict__ hs,  // [128][65]
                                        const float* __restrict__ W,   // [128][128]
                                        int ty, int tx, float acc[4][8]){
    const float4* W4 = (const float4*)W;
    int eb = (ty<<2);
    float a0 = hs[eb+0], a1 = hs[eb+1], a2 = hs[eb+2], a3 = hs[eb+3];
    float4 w0 = __ldg(W4 + (tx<<1));
    float4 w1 = __ldg(W4 + (tx<<1) + 1);
    #pragma unroll 2
    for (int k = 0; k < 127; ++k){
        int o = (k+1)*65 + eb;
        float b0 = hs[o+0], b1 = hs[o+1], b2 = hs[o+2], b3 = hs[o+3];
        float4 w0n = __ldg(W4 + (k+1)*32 + (tx<<1));
        float4 w1n = __ldg(W4 + (k+1)*32 + (tx<<1) + 1);
        float4 av = make_float4(a0, a1, a2, a3);
        fma_tile8x4(acc, av, w0, w1);
        a0 = b0; a1 = b1; a2 = b2; a3 = b3; w0 = w0n; w1 = w1n;
    }
    float4 av = make_float4(a0, a1, a2, a3);
    fma_tile8x4(acc, av, w0, w1);
}

__global__ void __launch_bounds__(256, 1)
edge_kernel(const int* __restrict__ ei, const float* __restrict__ eattr,
            const float* __restrict__ Wa,   // raw a_w1 for layer l
            const float* __restrict__ ab1, const float* __restrict__ aw2, const float* __restrict__ ab2,
            const float* __restrict__ vw2, const float* __restrict__ vb2,
            const float* __restrict__ sw2, const float* __restrict__ sb2,
            const float* __restrict__ g2,  const float* __restrict__ b2,
            int l, int E)
{
    extern __shared__ float sh[];
    float* shmsg  = sh;                         // 192*64
    float* shhs   = shmsg + 192*64;             // 128*65
    float* shmean = shhs + 128*65;              // 64
    float* shsd   = shmean + 64;                // 64
    float* shattn = shsd + 64;                  // 64
    float* shrel  = shattn + 64;                // 64*3
    int*   shdst  = (int*)(shrel + 192);        // 64

    const float* Ws  = g_Ws  + l*MM*HH;
    const float* Wv  = g_Wv  + l*MM*HH;
    const float* bs  = g_bs  + l*HH;
    const float* bv  = g_bv  + l*HH;
    const float* csa = g_csa + l*HH;

    const int tid = threadIdx.x;
    const int tx = tid & 15, ty = tid >> 4;
    const int base = blockIdx.x << 6;

    // ---- stage 1: gather + LN stats + msg_hat into shared ----
    {
        int el = tid >> 2, r = tid & 3;
        int e = base + el;
        int ec = (e < E) ? e : (E-1);
        int src = ei[ec], dst = ei[E + ec];
        float vals[48]; float s = 0.f, q = 0.f;
        #pragma unroll
        for (int i = 0; i < 48; ++i){
            int k = (i<<2) + r;
            float v = (k < HH) ? g_xn[src*HH + k] : eattr[ec*DD + (k-HH)];
            vals[i] = v; s += v; q += v*v;
        }
        s += __shfl_xor_sync(0xffffffffu, s, 1); s += __shfl_xor_sync(0xffffffffu, s, 2);
        q += __shfl_xor_sync(0xffffffffu, q, 1); q += __shfl_xor_sync(0xffffffffu, q, 2);
        float mean = s*(1.f/192.f);
        float var  = fmaxf(q*(1.f/192.f) - mean*mean, 0.f);
        float sd   = sqrtf(var + EPSV);
        float rstd = 1.f/sd;
        #pragma unroll
        for (int i = 0; i < 48; ++i){
            int k = (i<<2) + r;
            shmsg[k*64 + el] = (vals[i]-mean)*rstd;
        }
        if (r == 0){
            shmean[el] = mean; shsd[el] = sd; shdst[el] = dst;
            float a0 = g_pn[src*3+0], a1 = g_pn[src*3+1], a2 = g_pn[src*3+2];
            float d0 = a0 - g_pn[dst*3+0];
            float d1 = a1 - g_pn[dst*3+1];
            float d2 = a2 - g_pn[dst*3+2];
            float dist = fmaxf(sqrtf(d0*d0 + d1*d1 + d2*d2), 1e-6f);
            float inv = 1.f/dist;
            shrel[el*3+0] = d0*inv; shrel[el*3+1] = d1*inv; shrel[el*3+2] = d2*inv;
        }
    }
    __syncthreads();

    // ---- phase A: attention (raw msg path via mean/std reconstruction) ----
    {
        float acc[4][8];
        zero_acc(acc);
        gemm_msg<192>(shmsg, Wa, ty, tx, acc);
        float ab2v = __ldg(ab2);
        #pragma unroll
        for (int i = 0; i < 4; ++i){
            int el = (ty<<2) + i;
            float mn = shmean[el], sd = shsd[el];
            float part = 0.f;
            #pragma unroll
            for (int j = 0; j < 8; ++j){
                int c = (tx<<3) + j;
                float v = sd*acc[i][j] + mn*__ldg(csa+c) + __ldg(ab1+c);
                part += siluf_(v)*__ldg(aw2+c);
            }
            #pragma unroll
            for (int off = 8; off; off >>= 1)
                part += __shfl_down_sync(0xffffffffu, part, off, 16);
            if (tx == 0) shattn[el] = sigmoidf_(part + ab2v);
        }
    }

    // ---- phase V: vector weight + vec atomics ----
    {
        float acc[4][8];
        zero_acc(acc);
        gemm_msg<192>(shmsg, Wv, ty, tx, acc);
        float vb2v = __ldg(vb2);
        #pragma unroll
        for (int i = 0; i < 4; ++i){
            int el = (ty<<2) + i;
            float part = 0.f;
            #pragma unroll
            for (int j = 0; j < 8; ++j){
                int c = (tx<<3) + j;
                float v = acc[i][j] + __ldg(bv+c);
                part += siluf_(v)*__ldg(vw2+c);
            }
            #pragma unroll
            for (int off = 8; off; off >>= 1)
                part += __shfl_down_sync(0xffffffffu, part, off, 16);
            if (tx == 0){
                int e = base + el;
                if (e < E){
                    float f = (part + vb2v)*shattn[el];
                    int dd = shdst[el];
                    atomicAdd(&g_va[dd*3+0], f*shrel[el*3+0]);
                    atomicAdd(&g_va[dd*3+1], f*shrel[el*3+1]);
                    atomicAdd(&g_va[dd*3+2], f*shrel[el*3+2]);
                }
            }
        }
    }

    // ---- phase S: first scalar GEMM -> silu -> shared ----
    {
        float acc[4][8];
        zero_acc(acc);
        gemm_msg<192>(shmsg, Ws, ty, tx, acc);
        __syncthreads();   // ensure everyone is done reading shmsg region? (shhs is separate; sync for attn use below)
        #pragma unroll
        for (int i = 0; i < 4; ++i){
            int el = (ty<<2) + i;
            #pragma unroll
            for (int j = 0; j < 8; ++j){
                int c = (tx<<3) + j;
                shhs[c*65 + el] = siluf_(acc[i][j] + __ldg(bs+c));
            }
        }
    }
    __syncthreads();

    // ---- GEMM2 + LN + attn scale + scatter ----
    {
        float acc[4][8];
        zero_acc(acc);
        gemm_hs(shhs, sw2, ty, tx, acc);
        #pragma unroll
        for (int i = 0; i < 4; ++i){
            int el = (ty<<2) + i;
            float s = 0.f, q = 0.f;
            #pragma unroll
            for (int j = 0; j < 8; ++j){
                int c = (tx<<3) + j;
                float v = acc[i][j] + __ldg(sb2+c);
                acc[i][j] = v; s += v; q += v*v;
            }
            #pragma unroll
            for (int off = 8; off; off >>= 1){
                s += __shfl_xor_sync(0xffffffffu, s, off, 16);
                q += __shfl_xor_sync(0xffffffffu, q, off, 16);
            }
            float mean = s*(1.f/128.f);
            float var  = fmaxf(q*(1.f/128.f) - mean*mean, 0.f);
            float rstd = rsqrtf(var + EPSV);
            int e = base + el;
            if (e < E){
                float at = shattn[el];
                int dd = shdst[el];
                #pragma unroll
                for (int j = 0; j < 8; ++j){
                    int c = (tx<<3) + j;
                    float sc = ((acc[i][j]-mean)*rstd*__ldg(g2+c) + __ldg(b2+c))*at;
                    atomicAdd(&g_sa[dd*HH + c], sc);
                }
            }
        }
    }
}

// ---------------- node update: gate GEMM + blend + pos update ----------------
__global__ void node_update(const float* __restrict__ gw, const float* __restrict__ gb, int N){
    int w = (blockIdx.x*blockDim.x + threadIdx.x) >> 5;
    int lane = threadIdx.x & 31;
    if (w >= N) return;
    float xr[8];
    #pragma unroll
    for (int j = 0; j < 4; ++j) xr[j]   = g_xn[w*HH + (j<<5) + lane];
    #pragma unroll
    for (int j = 0; j < 4; ++j) xr[4+j] = g_sa[w*HH + (j<<5) + lane];
    float acc[4] = {0.f,0.f,0.f,0.f};
    const float4* W4 = (const float4*)gw;
    #pragma unroll 4
    for (int k = 0; k < 256; ++k){
        float xv = __shfl_sync(0xffffffffu, xr[k>>5], k & 31);
        float4 wv = __ldg(W4 + k*32 + lane);
        acc[0] = fmaf(xv, wv.x, acc[0]);
        acc[1] = fmaf(xv, wv.y, acc[1]);
        acc[2] = fmaf(xv, wv.z, acc[2]);
        acc[3] = fmaf(xv, wv.w, acc[3]);
    }
    int cb = lane << 2;
    #pragma unroll
    for (int jj = 0; jj < 4; ++jj){
        int c = cb + jj;
        float gt = sigmoidf_(acc[jj] + __ldg(gb+c));
        float xnv = g_xn[w*HH+c], sav = g_sa[w*HH+c];
        g_x[w*HH+c] = xnv + gt*(sav - xnv);
    }
    if (lane < 3){
        float p = g_pn[w*3+lane] + g_va[w*3+lane];
        g_p[w*3+lane] = fminf(fmaxf(p, -10.f), 10.f);
    }
}

// ---------------- energy head + output ----------------
__global__ void energy_kernel(const float* __restrict__ ew1, const float* __restrict__ eb1,
                              const float* __restrict__ ew2, const float* __restrict__ eb2,
                              float* __restrict__ out, int N, int out_size){
    int w = (blockIdx.x*blockDim.x + threadIdx.x) >> 5;
    int lane = threadIdx.x & 31;
    if (w >= N) return;
    float xr[4];
    #pragma unroll
    for (int j = 0; j < 4; ++j) xr[j] = g_x[w*HH + (j<<5) + lane];
    float acc[4] = {0.f,0.f,0.f,0.f};
    const float4* W14 = (const float4*)ew1;
    #pragma unroll 4
    for (int k = 0; k < 128; ++k){
        float xv = __shfl_sync(0xffffffffu, xr[k>>5], k & 31);
        float4 wv = __ldg(W14 + k*32 + lane);
        acc[0] = fmaf(xv, wv.x, acc[0]);
        acc[1] = fmaf(xv, wv.y, acc[1]);
        acc[2] = fmaf(xv, wv.z, acc[2]);
        acc[3] = fmaf(xv, wv.w, acc[3]);
    }
    float h[4];
    #pragma unroll
    for (int jj = 0; jj < 4; ++jj)
        h[jj] = fmaxf(acc[jj] + __ldg(eb1 + (lane<<2) + jj), 0.f);
    float acc2[4] = {0.f,0.f,0.f,0.f};
    const float4* W24 = (const float4*)ew2;
    #pragma unroll 4
    for (int k = 0; k < 128; ++k){
        float hk = __shfl_sync(0xffffffffu, h[k & 3], k >> 2);
        float4 wv = __ldg(W24 + k*32 + lane);
        acc2[0] = fmaf(hk, wv.x, acc2[0]);
        acc2[1] = fmaf(hk, wv.y, acc2[1]);
        acc2[2] = fmaf(hk, wv.z, acc2[2]);
        acc2[3] = fmaf(hk, wv.w, acc2[3]);
    }
    #pragma unroll
    for (int jj = 0; jj < 4; ++jj){
        int c = (lane<<2) + jj;
        out[w*HH + c] = acc2[jj] + __ldg(eb2 + c);
    }
    if (lane < 3){
        int oi = N*HH + w*3 + lane;
        if (oi < out_size)
            out[oi] = g_p[w*3 + lane];
    }
}

// ---------------- host launcher ----------------
extern "C" void kernel_launch(void* const* d_in, const int* in_sizes, int n_in,
                              void* d_out, int out_size){
    const float* x    = (const float*)d_in[0];
    const float* pos  = (const float*)d_in[1];
    const int*   ei   = (const int*)  d_in[2];
    const float* eat  = (const float*)d_in[3];
    const float* lxg  = (const float*)d_in[4];
    const float* lxb  = (const float*)d_in[5];
    const float* lpg  = (const float*)d_in[6];
    const float* lpb  = (const float*)d_in[7];
    const float* sl1g = (const float*)d_in[8];
    const float* sl1b = (const float*)d_in[9];
    const float* sw1  = (const float*)d_in[10];
    const float* sb1  = (const float*)d_in[11];
    const float* sw2  = (const float*)d_in[12];
    const float* sb2  = (const float*)d_in[13];
    const float* sl2g = (const float*)d_in[14];
    const float* sl2b = (const float*)d_in[15];
    const float* vlg  = (const float*)d_in[16];
    const float* vlb  = (const float*)d_in[17];
    const float* vw1  = (const float*)d_in[18];
    const float* vb1  = (const float*)d_in[19];
    const float* vw2  = (const float*)d_in[20];
    const float* vb2  = (const float*)d_in[21];
    const float* aw1  = (const float*)d_in[22];
    const float* ab1  = (const float*)d_in[23];
    const float* aw2  = (const float*)d_in[24];
    const float* ab2  = (const float*)d_in[25];
    const float* gw   = (const float*)d_in[26];
    const float* gb   = (const float*)d_in[27];
    const float* ew1  = (const float*)d_in[28];
    const float* eb1  = (const float*)d_in[29];
    const float* ew2  = (const float*)d_in[30];
    const float* eb2  = (const float*)d_in[31];

    int N = in_sizes[0] / HH;
    int E = in_sizes[2] / 2;

    const int SMEM = (192*64 + 128*65 + 64 + 64 + 64 + 64*3 + 64) * 4;
    cudaFuncSetAttribute(edge_kernel, cudaFuncAttributeMaxDynamicSharedMemorySize, SMEM);

    copy_init<<<(N*HH + 255)/256, 256>>>(x, pos, N);
    fold_w<<<(LLAYERS*MM*HH + 255)/256, 256>>>(sw1, sl1g, vw1, vlg);
    fold_bias<<<(LLAYERS*HH + 255)/256, 256>>>(sw1, sb1, sl1b, vw1, vb1, vlb, aw1);

    for (int l = 0; l < LLAYERS; ++l){
        zero_aggr<<<(N*HH + 255)/256, 256>>>(N);
        ln_node<<<(N + 7)/8, 256>>>(lxg + l*HH, lxb + l*HH, lpg + l*3, lpb + l*3, N);
        edge_kernel<<<(E + 63)/64, 256, SMEM>>>(
            ei, eat,
            aw1 + l*MM*HH,
            ab1 + l*HH, aw2 + l*HH, ab2 + l,
            vw2 + l*HH, vb2 + l,
            sw2 + l*HH*HH, sb2 + l*HH,
            sl2g + l*HH, sl2b + l*HH,
            l, E);
        node_update<<<(N + 7)/8, 256>>>(gw + l*2*HH*HH, gb + l*HH, N);
    }
    energy_kernel<<<(N + 7)/8, 256>>>(ew1, eb1, ew2, eb2, (float*)d_out, N, out_size);
}

// round 6
// speedup vs baseline: 1.0169x; 1.0169x over previous
#include <cuda_runtime.h>
#include <math.h>

#define NN 25000
#define EE 400000
#define HH 128
#define DD 64
#define MM 192
#define LLAYERS 3
#define EPSV 1e-6f

typedef unsigned long long u64;

// ---------------- persistent device scratch ----------------
__device__ float g_x [NN*HH];
__device__ float g_p [NN*3];
__device__ float g_xn[NN*HH];
__device__ float g_pn[NN*3];
__device__ float g_sa[NN*HH];
__device__ float g_va[NN*3];
__device__ float g_Ws [LLAYERS*MM*HH];
__device__ float g_Wv [LLAYERS*MM*HH];
__device__ float g_bs [LLAYERS*HH];
__device__ float g_bv [LLAYERS*HH];
__device__ float g_csa[LLAYERS*HH];

__device__ __forceinline__ float sigmoidf_(float x){ return 1.f/(1.f + expf(-x)); }
__device__ __forceinline__ float siluf_(float x){ return x/(1.f + expf(-x)); }

// ---- packed f32x2 helpers ----
__device__ __forceinline__ u64 pack2(float x){
    u64 r; asm("mov.b64 %0, {%1, %1};" : "=l"(r) : "f"(x)); return r;
}
__device__ __forceinline__ void fma2(u64 &d, u64 a, u64 b){
    asm("fma.rn.f32x2 %0, %1, %2, %0;" : "+l"(d) : "l"(a), "l"(b));
}
__device__ __forceinline__ float2 unpack2(u64 v){
    float2 f; asm("mov.b64 {%0, %1}, %2;" : "=f"(f.x), "=f"(f.y) : "l"(v)); return f;
}
__device__ __forceinline__ void zero_acc2(u64 acc[4][4]){
    #pragma unroll
    for (int i = 0; i < 4; ++i){
        #pragma unroll
        for (int j = 0; j < 4; ++j) acc[i][j] = 0ull;
    }
}

// ---------------- small prep kernels ----------------
__global__ void copy_init(const float* __restrict__ x, const float* __restrict__ pos, int N){
    int i = blockIdx.x*blockDim.x + threadIdx.x;
    if (i < N*HH) g_x[i] = x[i];
    if (i < N*3)  g_p[i] = pos[i];
}

__global__ void zero_aggr(int N){
    int i = blockIdx.x*blockDim.x + threadIdx.x;
    if (i < N*HH) g_sa[i] = 0.f;
    if (i < N*3)  g_va[i] = 0.f;
}

__global__ void fold_w(const float* __restrict__ sw1, const float* __restrict__ sg,
                       const float* __restrict__ vw1, const float* __restrict__ vg){
    int i = blockIdx.x*blockDim.x + threadIdx.x;
    if (i >= LLAYERS*MM*HH) return;
    int l = i/(MM*HH);
    int k = (i/HH)%MM;
    g_Ws[i] = sg[l*MM+k]*sw1[i];
    g_Wv[i] = vg[l*MM+k]*vw1[i];
}

__global__ void fold_bias(const float* __restrict__ sw1, const float* __restrict__ sb1, const float* __restrict__ slb,
                          const float* __restrict__ vw1, const float* __restrict__ vb1, const float* __restrict__ vlb,
                          const float* __restrict__ aw1){
    int i = blockIdx.x*blockDim.x + threadIdx.x;
    if (i >= LLAYERS*HH) return;
    int l = i/HH, c = i%HH;
    float bs = sb1[i], bv = vb1[i], cs = 0.f;
    for (int k = 0; k < MM; ++k){
        float swv = sw1[(l*MM+k)*HH + c];
        float vwv = vw1[(l*MM+k)*HH + c];
        bs += slb[l*MM+k]*swv;
        bv += vlb[l*MM+k]*vwv;
        cs += aw1[(l*MM+k)*HH + c];
    }
    g_bs[i] = bs; g_bv[i] = bv; g_csa[i] = cs;
}

// per-node LayerNorm of x (H=128) and pos (3). warp per node.
__global__ void ln_node(const float* __restrict__ lxg, const float* __restrict__ lxb,
                        const float* __restrict__ lpg, const float* __restrict__ lpb, int N){
    int w = (blockIdx.x*blockDim.x + threadIdx.x) >> 5;
    int lane = threadIdx.x & 31;
    if (w >= N) return;
    float v[4]; float s = 0.f, q = 0.f;
    #pragma unroll
    for (int j = 0; j < 4; ++j){
        v[j] = g_x[w*HH + (j<<5) + lane];
        s += v[j]; q += v[j]*v[j];
    }
    #pragma unroll
    for (int o = 16; o; o >>= 1){
        s += __shfl_xor_sync(0xffffffffu, s, o);
        q += __shfl_xor_sync(0xffffffffu, q, o);
    }
    float mean = s*(1.f/128.f);
    float var  = fmaxf(q*(1.f/128.f) - mean*mean, 0.f);
    float rstd = rsqrtf(var + EPSV);
    #pragma unroll
    for (int j = 0; j < 4; ++j){
        int c = (j<<5) + lane;
        g_xn[w*HH + c] = (v[j]-mean)*rstd*lxg[c] + lxb[c];
    }
    if (lane == 0){
        float p0 = g_p[w*3+0], p1 = g_p[w*3+1], p2 = g_p[w*3+2];
        float m = (p0+p1+p2)*(1.f/3.f);
        float d0 = p0-m, d1 = p1-m, d2 = p2-m;
        float varp = (d0*d0+d1*d1+d2*d2)*(1.f/3.f);
        float rs = rsqrtf(varp + EPSV);
        g_pn[w*3+0] = d0*rs*lpg[0] + lpb[0];
        g_pn[w*3+1] = d1*rs*lpg[1] + lpb[1];
        g_pn[w*3+2] = d2*rs*lpg[2] + lpb[2];
    }
}

// ---------------- fused edge kernel ----------------
// 64 edges per block, 256 threads (16x16): thread tile = 4 edges x 8 cols.
// Packed f32x2: acc[i][jp] holds cols (tx*8+2jp, tx*8+2jp+1) for edge-row i.
// NOTE: a 128-float weight row = 32 x ulonglong2 (16B each). Row stride = 32.

template<int K>
__device__ __forceinline__ void gemm_msg2(const float* __restrict__ shmsg,
                                          const float* __restrict__ W,
                                          int ty, int tx, u64 acc[4][4]){
    const float4* msg4 = (const float4*)shmsg;        // [K][16] float4 (row = k)
    const ulonglong2* W2 = (const ulonglong2*)W;      // [K][32] ulonglong2
    float4 a  = msg4[ty];
    ulonglong2 w0 = __ldg(W2 + (tx<<1));
    ulonglong2 w1 = __ldg(W2 + (tx<<1) + 1);
    #pragma unroll 2
    for (int k = 0; k < K-1; ++k){
        float4 an  = msg4[(k+1)*16 + ty];
        ulonglong2 w0n = __ldg(W2 + (k+1)*32 + (tx<<1));
        ulonglong2 w1n = __ldg(W2 + (k+1)*32 + (tx<<1) + 1);
        u64 a2[4] = {pack2(a.x), pack2(a.y), pack2(a.z), pack2(a.w)};
        #pragma unroll
        for (int i = 0; i < 4; ++i){
            fma2(acc[i][0], a2[i], w0.x);
            fma2(acc[i][1], a2[i], w0.y);
            fma2(acc[i][2], a2[i], w1.x);
            fma2(acc[i][3], a2[i], w1.y);
        }
        a = an; w0 = w0n; w1 = w1n;
    }
    {
        u64 a2[4] = {pack2(a.x), pack2(a.y), pack2(a.z), pack2(a.w)};
        #pragma unroll
        for (int i = 0; i < 4; ++i){
            fma2(acc[i][0], a2[i], w0.x);
            fma2(acc[i][1], a2[i], w0.y);
            fma2(acc[i][2], a2[i], w1.x);
            fma2(acc[i][3], a2[i], w1.y);
        }
    }
}

__device__ __forceinline__ void gemm_hs2(const float* __restrict__ hs,  // [128][65]
                                         const float* __restrict__ W,   // [128][128]
                                         int ty, int tx, u64 acc[4][4]){
    const ulonglong2* W2 = (const ulonglong2*)W;      // [128][32] ulonglong2
    int eb = (ty<<2);
    float a0 = hs[eb+0], a1 = hs[eb+1], a2v = hs[eb+2], a3 = hs[eb+3];
    ulonglong2 w0 = __ldg(W2 + (tx<<1));
    ulonglong2 w1 = __ldg(W2 + (tx<<1) + 1);
    #pragma unroll 2
    for (int k = 0; k < 127; ++k){
        int o = (k+1)*65 + eb;
        float b0 = hs[o+0], b1 = hs[o+1], b2 = hs[o+2], b3 = hs[o+3];
        ulonglong2 w0n = __ldg(W2 + (k+1)*32 + (tx<<1));
        ulonglong2 w1n = __ldg(W2 + (k+1)*32 + (tx<<1) + 1);
        u64 ap[4] = {pack2(a0), pack2(a1), pack2(a2v), pack2(a3)};
        #pragma unroll
        for (int i = 0; i < 4; ++i){
            fma2(acc[i][0], ap[i], w0.x);
            fma2(acc[i][1], ap[i], w0.y);
            fma2(acc[i][2], ap[i], w1.x);
            fma2(acc[i][3], ap[i], w1.y);
        }
        a0 = b0; a1 = b1; a2v = b2; a3 = b3; w0 = w0n; w1 = w1n;
    }
    {
        u64 ap[4] = {pack2(a0), pack2(a1), pack2(a2v), pack2(a3)};
        #pragma unroll
        for (int i = 0; i < 4; ++i){
            fma2(acc[i][0], ap[i], w0.x);
            fma2(acc[i][1], ap[i], w0.y);
            fma2(acc[i][2], ap[i], w1.x);
            fma2(acc[i][3], ap[i], w1.y);
        }
    }
}

__global__ void __launch_bounds__(256, 2)
edge_kernel(const int* __restrict__ ei, const float* __restrict__ eattr,
            const float* __restrict__ Wa,   // raw a_w1 for layer l
            const float* __restrict__ ab1, const float* __restrict__ aw2, const float* __restrict__ ab2,
            const float* __restrict__ vw2, const float* __restrict__ vb2,
            const float* __restrict__ sw2, const float* __restrict__ sb2,
            const float* __restrict__ g2,  const float* __restrict__ b2,
            int l, int E)
{
    extern __shared__ float sh[];
    float* shmsg  = sh;                         // 192*64
    float* shhs   = shmsg + 192*64;             // 128*65
    float* shmean = shhs + 128*65;              // 64
    float* shsd   = shmean + 64;                // 64
    float* shattn = shsd + 64;                  // 64
    float* shrel  = shattn + 64;                // 64*3
    int*   shdst  = (int*)(shrel + 192);        // 64

    const float* Ws  = g_Ws  + l*MM*HH;
    const float* Wv  = g_Wv  + l*MM*HH;
    const float* bs  = g_bs  + l*HH;
    const float* bv  = g_bv  + l*HH;
    const float* csa = g_csa + l*HH;

    const int tid = threadIdx.x;
    const int tx = tid & 15, ty = tid >> 4;
    const int base = blockIdx.x << 6;

    // ---- stage 1: gather + LN stats + msg_hat into shared ----
    {
        int el = tid >> 2, r = tid & 3;
        int e = base + el;
        int ec = (e < E) ? e : (E-1);
        int src = ei[ec], dst = ei[E + ec];
        float vals[48]; float s = 0.f, q = 0.f;
        #pragma unroll
        for (int i = 0; i < 48; ++i){
            int k = (i<<2) + r;
            float v = (k < HH) ? g_xn[src*HH + k] : eattr[ec*DD + (k-HH)];
            vals[i] = v; s += v; q += v*v;
        }
        s += __shfl_xor_sync(0xffffffffu, s, 1); s += __shfl_xor_sync(0xffffffffu, s, 2);
        q += __shfl_xor_sync(0xffffffffu, q, 1); q += __shfl_xor_sync(0xffffffffu, q, 2);
        float mean = s*(1.f/192.f);
        float var  = fmaxf(q*(1.f/192.f) - mean*mean, 0.f);
        float sd   = sqrtf(var + EPSV);
        float rstd = 1.f/sd;
        #pragma unroll
        for (int i = 0; i < 48; ++i){
            int k = (i<<2) + r;
            shmsg[k*64 + el] = (vals[i]-mean)*rstd;
        }
        if (r == 0){
            shmean[el] = mean; shsd[el] = sd; shdst[el] = dst;
            float a0 = g_pn[src*3+0], a1 = g_pn[src*3+1], a2 = g_pn[src*3+2];
            float d0 = a0 - g_pn[dst*3+0];
            float d1 = a1 - g_pn[dst*3+1];
            float d2 = a2 - g_pn[dst*3+2];
            float dist = fmaxf(sqrtf(d0*d0 + d1*d1 + d2*d2), 1e-6f);
            float inv = 1.f/dist;
            shrel[el*3+0] = d0*inv; shrel[el*3+1] = d1*inv; shrel[el*3+2] = d2*inv;
        }
    }
    __syncthreads();

    // ---- phase A: attention (raw msg path via mean/std reconstruction) ----
    {
        u64 acc[4][4];
        zero_acc2(acc);
        gemm_msg2<192>(shmsg, Wa, ty, tx, acc);
        float ab2v = __ldg(ab2);
        #pragma unroll
        for (int i = 0; i < 4; ++i){
            int el = (ty<<2) + i;
            float mn = shmean[el], sd = shsd[el];
            float part = 0.f;
            #pragma unroll
            for (int jp = 0; jp < 4; ++jp){
                float2 v2 = unpack2(acc[i][jp]);
                int c = (tx<<3) + (jp<<1);
                float va = sd*v2.x + mn*__ldg(csa+c)   + __ldg(ab1+c);
                float vb = sd*v2.y + mn*__ldg(csa+c+1) + __ldg(ab1+c+1);
                part += siluf_(va)*__ldg(aw2+c);
                part += siluf_(vb)*__ldg(aw2+c+1);
            }
            #pragma unroll
            for (int off = 8; off; off >>= 1)
                part += __shfl_down_sync(0xffffffffu, part, off, 16);
            if (tx == 0) shattn[el] = sigmoidf_(part + ab2v);
        }
    }

    // ---- phase V: vector weight + vec atomics ----
    {
        u64 acc[4][4];
        zero_acc2(acc);
        gemm_msg2<192>(shmsg, Wv, ty, tx, acc);
        float vb2v = __ldg(vb2);
        #pragma unroll
        for (int i = 0; i < 4; ++i){
            int el = (ty<<2) + i;
            float part = 0.f;
            #pragma unroll
            for (int jp = 0; jp < 4; ++jp){
                float2 v2 = unpack2(acc[i][jp]);
                int c = (tx<<3) + (jp<<1);
                part += siluf_(v2.x + __ldg(bv+c))  *__ldg(vw2+c);
                part += siluf_(v2.y + __ldg(bv+c+1))*__ldg(vw2+c+1);
            }
            #pragma unroll
            for (int off = 8; off; off >>= 1)
                part += __shfl_down_sync(0xffffffffu, part, off, 16);
            if (tx == 0){
                int e = base + el;
                if (e < E){
                    float f = (part + vb2v)*shattn[el];
                    int dd = shdst[el];
                    atomicAdd(&g_va[dd*3+0], f*shrel[el*3+0]);
                    atomicAdd(&g_va[dd*3+1], f*shrel[el*3+1]);
                    atomicAdd(&g_va[dd*3+2], f*shrel[el*3+2]);
                }
            }
        }
    }

    // ---- phase S: first scalar GEMM -> silu -> shared ----
    {
        u64 acc[4][4];
        zero_acc2(acc);
        gemm_msg2<192>(shmsg, Ws, ty, tx, acc);
        #pragma unroll
        for (int i = 0; i < 4; ++i){
            int el = (ty<<2) + i;
            #pragma unroll
            for (int jp = 0; jp < 4; ++jp){
                float2 v2 = unpack2(acc[i][jp]);
                int c = (tx<<3) + (jp<<1);
                shhs[c*65 + el]     = siluf_(v2.x + __ldg(bs+c));
                shhs[(c+1)*65 + el] = siluf_(v2.y + __ldg(bs+c+1));
            }
        }
    }
    __syncthreads();

    // ---- GEMM2 + LN + attn scale + scatter ----
    {
        u64 acc[4][4];
        zero_acc2(acc);
        gemm_hs2(shhs, sw2, ty, tx, acc);
        #pragma unroll
        for (int i = 0; i < 4; ++i){
            int el = (ty<<2) + i;
            float v[8];
            float s = 0.f, q = 0.f;
            #pragma unroll
            for (int jp = 0; jp < 4; ++jp){
                float2 v2 = unpack2(acc[i][jp]);
                int c = (tx<<3) + (jp<<1);
                v[jp*2]   = v2.x + __ldg(sb2+c);
                v[jp*2+1] = v2.y + __ldg(sb2+c+1);
                s += v[jp*2] + v[jp*2+1];
                q += v[jp*2]*v[jp*2] + v[jp*2+1]*v[jp*2+1];
            }
            #pragma unroll
            for (int off = 8; off; off >>= 1){
                s += __shfl_xor_sync(0xffffffffu, s, off, 16);
                q += __shfl_xor_sync(0xffffffffu, q, off, 16);
            }
            float mean = s*(1.f/128.f);
            float var  = fmaxf(q*(1.f/128.f) - mean*mean, 0.f);
            float rstd = rsqrtf(var + EPSV);
            int e = base + el;
            if (e < E){
                float at = shattn[el];
                int dd = shdst[el];
                #pragma unroll
                for (int j = 0; j < 8; ++j){
                    int c = (tx<<3) + j;
                    float sc = ((v[j]-mean)*rstd*__ldg(g2+c) + __ldg(b2+c))*at;
                    atomicAdd(&g_sa[dd*HH + c], sc);
                }
            }
        }
    }
}

// ---------------- node update: gate GEMM + blend + pos update ----------------
__global__ void node_update(const float* __restrict__ gw, const float* __restrict__ gb, int N){
    int w = (blockIdx.x*blockDim.x + threadIdx.x) >> 5;
    int lane = threadIdx.x & 31;
    if (w >= N) return;
    float xr[8];
    #pragma unroll
    for (int j = 0; j < 4; ++j) xr[j]   = g_xn[w*HH + (j<<5) + lane];
    #pragma unroll
    for (int j = 0; j < 4; ++j) xr[4+j] = g_sa[w*HH + (j<<5) + lane];
    float acc[4] = {0.f,0.f,0.f,0.f};
    const float4* W4 = (const float4*)gw;
    #pragma unroll 4
    for (int k = 0; k < 256; ++k){
        float xv = __shfl_sync(0xffffffffu, xr[k>>5], k & 31);
        float4 wv = __ldg(W4 + k*32 + lane);
        acc[0] = fmaf(xv, wv.x, acc[0]);
        acc[1] = fmaf(xv, wv.y, acc[1]);
        acc[2] = fmaf(xv, wv.z, acc[2]);
        acc[3] = fmaf(xv, wv.w, acc[3]);
    }
    int cb = lane << 2;
    #pragma unroll
    for (int jj = 0; jj < 4; ++jj){
        int c = cb + jj;
        float gt = sigmoidf_(acc[jj] + __ldg(gb+c));
        float xnv = g_xn[w*HH+c], sav = g_sa[w*HH+c];
        g_x[w*HH+c] = xnv + gt*(sav - xnv);
    }
    if (lane < 3){
        float p = g_pn[w*3+lane] + g_va[w*3+lane];
        g_p[w*3+lane] = fminf(fmaxf(p, -10.f), 10.f);
    }
}

// ---------------- energy head + output ----------------
__global__ void energy_kernel(const float* __restrict__ ew1, const float* __restrict__ eb1,
                              const float* __restrict__ ew2, const float* __restrict__ eb2,
                              float* __restrict__ out, int N, int out_size){
    int w = (blockIdx.x*blockDim.x + threadIdx.x) >> 5;
    int lane = threadIdx.x & 31;
    if (w >= N) return;
    float xr[4];
    #pragma unroll
    for (int j = 0; j < 4; ++j) xr[j] = g_x[w*HH + (j<<5) + lane];
    float acc[4] = {0.f,0.f,0.f,0.f};
    const float4* W14 = (const float4*)ew1;
    #pragma unroll 4
    for (int k = 0; k < 128; ++k){
        float xv = __shfl_sync(0xffffffffu, xr[k>>5], k & 31);
        float4 wv = __ldg(W14 + k*32 + lane);
        acc[0] = fmaf(xv, wv.x, acc[0]);
        acc[1] = fmaf(xv, wv.y, acc[1]);
        acc[2] = fmaf(xv, wv.z, acc[2]);
        acc[3] = fmaf(xv, wv.w, acc[3]);
    }
    float h[4];
    #pragma unroll
    for (int jj = 0; jj < 4; ++jj)
        h[jj] = fmaxf(acc[jj] + __ldg(eb1 + (lane<<2) + jj), 0.f);
    float acc2[4] = {0.f,0.f,0.f,0.f};
    const float4* W24 = (const float4*)ew2;
    #pragma unroll 4
    for (int k = 0; k < 128; ++k){
        float hk = __shfl_sync(0xffffffffu, h[k & 3], k >> 2);
        float4 wv = __ldg(W24 + k*32 + lane);
        acc2[0] = fmaf(hk, wv.x, acc2[0]);
        acc2[1] = fmaf(hk, wv.y, acc2[1]);
        acc2[2] = fmaf(hk, wv.z, acc2[2]);
        acc2[3] = fmaf(hk, wv.w, acc2[3]);
    }
    #pragma unroll
    for (int jj = 0; jj < 4; ++jj){
        int c = (lane<<2) + jj;
        out[w*HH + c] = acc2[jj] + __ldg(eb2 + c);
    }
    if (lane < 3){
        int oi = N*HH + w*3 + lane;
        if (oi < out_size)
            out[oi] = g_p[w*3 + lane];
    }
}

// ---------------- host launcher ----------------
extern "C" void kernel_launch(void* const* d_in, const int* in_sizes, int n_in,
                              void* d_out, int out_size){
    const float* x    = (const float*)d_in[0];
    const float* pos  = (const float*)d_in[1];
    const int*   ei   = (const int*)  d_in[2];
    const float* eat  = (const float*)d_in[3];
    const float* lxg  = (const float*)d_in[4];
    const float* lxb  = (const float*)d_in[5];
    const float* lpg  = (const float*)d_in[6];
    const float* lpb  = (const float*)d_in[7];
    const float* sl1g = (const float*)d_in[8];
    const float* sl1b = (const float*)d_in[9];
    const float* sw1  = (const float*)d_in[10];
    const float* sb1  = (const float*)d_in[11];
    const float* sw2  = (const float*)d_in[12];
    const float* sb2  = (const float*)d_in[13];
    const float* sl2g = (const float*)d_in[14];
    const float* sl2b = (const float*)d_in[15];
    const float* vlg  = (const float*)d_in[16];
    const float* vlb  = (const float*)d_in[17];
    const float* vw1  = (const float*)d_in[18];
    const float* vb1  = (const float*)d_in[19];
    const float* vw2  = (const float*)d_in[20];
    const float* vb2  = (const float*)d_in[21];
    const float* aw1  = (const float*)d_in[22];
    const float* ab1  = (const float*)d_in[23];
    const float* aw2  = (const float*)d_in[24];
    const float* ab2  = (const float*)d_in[25];
    const float* gw   = (const float*)d_in[26];
    const float* gb   = (const float*)d_in[27];
    const float* ew1  = (const float*)d_in[28];
    const float* eb1  = (const float*)d_in[29];
    const float* ew2  = (const float*)d_in[30];
    const float* eb2  = (const float*)d_in[31];

    int N = in_sizes[0] / HH;
    int E = in_sizes[2] / 2;

    const int SMEM = (192*64 + 128*65 + 64 + 64 + 64 + 64*3 + 64) * 4;
    cudaFuncSetAttribute(edge_kernel, cudaFuncAttributeMaxDynamicSharedMemorySize, SMEM);

    copy_init<<<(N*HH + 255)/256, 256>>>(x, pos, N);
    fold_w<<<(LLAYERS*MM*HH + 255)/256, 256>>>(sw1, sl1g, vw1, vlg);
    fold_bias<<<(LLAYERS*HH + 255)/256, 256>>>(sw1, sb1, sl1b, vw1, vb1, vlb, aw1);

    for (int l = 0; l < LLAYERS; ++l){
        zero_aggr<<<(N*HH + 255)/256, 256>>>(N);
        ln_node<<<(N + 7)/8, 256>>>(lxg + l*HH, lxb + l*HH, lpg + l*3, lpb + l*3, N);
        edge_kernel<<<(E + 63)/64, 256, SMEM>>>(
            ei, eat,
            aw1 + l*MM*HH,
            ab1 + l*HH, aw2 + l*HH, ab2 + l,
            vw2 + l*HH, vb2 + l,
            sw2 + l*HH*HH, sb2 + l*HH,
            sl2g + l*HH, sl2b + l*HH,
            l, E);
        node_update<<<(N + 7)/8, 256>>>(gw + l*2*HH*HH, gb + l*HH, N);
    }
    energy_kernel<<<(N + 7)/8, 256>>>(ew1, eb1, ew2, eb2, (float*)d_out, N, out_size);
}